// round 1
// baseline (speedup 1.0000x reference)
#include <cuda_runtime.h>
#include <math.h>

#define SEQ    2048
#define BATCH  2
#define TOK    4096    // BATCH*SEQ
#define DIM    1024
#define NHEAD  16
#define KVHEAD 4
#define HDIM   64
#define NLAYER 8
#define FF     4096
#define VOCAB  32000

// ---------------- scratch (no cudaMalloc allowed) ----------------
__device__ float g_h  [TOK * DIM];            // residual stream
__device__ float g_xn [TOK * DIM];            // rmsnorm output
__device__ float g_q  [TOK * NHEAD  * HDIM];
__device__ float g_k  [TOK * KVHEAD * HDIM];
__device__ float g_v  [TOK * KVHEAD * HDIM];
__device__ float g_att[TOK * NHEAD  * HDIM];
__device__ float g_f1 [TOK * FF];
__device__ float g_f3 [TOK * FF];
__device__ float g_cos[SEQ * 32];
__device__ float g_sin[SEQ * 32];

// ---------------- RoPE tables (YaRN-style) ----------------
__global__ void rope_init_kernel() {
    int t = blockIdx.x;      // position 0..SEQ-1
    int j = threadIdx.x;     // freq index 0..31
    double inv   = pow(10000.0, -(2.0 * j) / 64.0);
    double r     = 81920.0 * inv / (2.0 * M_PI);         // ROPE_MAX / wavelength
    double gamma = (r - 1.0) / 31.0;
    gamma = gamma < 0.0 ? 0.0 : (gamma > 1.0 ? 1.0 : gamma);
    double inv2  = inv * ((1.0 - gamma) / 40.0 + gamma);
    double c     = sqrt(0.1 * log(40.0) + 1.0);
    double ang   = (double)t * inv2 / c;
    g_cos[t * 32 + j] = (float)cos(ang);
    g_sin[t * 32 + j] = (float)sin(ang);
}

// ---------------- embedding gather ----------------
__global__ void embed_kernel(const int* __restrict__ ids,
                             const float* __restrict__ emb) {
    int t = blockIdx.x;
    const float* src = emb + (size_t)ids[t] * DIM;
    float* dst = g_h + (size_t)t * DIM;
    for (int d = threadIdx.x; d < DIM; d += blockDim.x) dst[d] = src[d];
}

// ---------------- rmsnorm (one block per row) ----------------
__global__ __launch_bounds__(256) void rmsnorm_kernel(
    const float* __restrict__ x, const float* __restrict__ w,
    float* __restrict__ o) {
    int row = blockIdx.x;
    int tid = threadIdx.x;
    const float* xr = x + (size_t)row * DIM;
    float s = 0.f;
    #pragma unroll
    for (int d = tid; d < DIM; d += 256) { float v = xr[d]; s += v * v; }
    #pragma unroll
    for (int off = 16; off; off >>= 1) s += __shfl_xor_sync(0xffffffffu, s, off);
    __shared__ float red[8];
    __shared__ float rsv;
    if ((tid & 31) == 0) red[tid >> 5] = s;
    __syncthreads();
    if (tid == 0) {
        float t = 0.f;
        #pragma unroll
        for (int i = 0; i < 8; i++) t += red[i];
        rsv = rsqrtf(t / (float)DIM + 1e-6f);
    }
    __syncthreads();
    float rs = rsv;
    for (int d = tid; d < DIM; d += 256)
        o[(size_t)row * DIM + d] = xr[d] * rs * w[d];
}

// ---------------- SGEMM: C[M,N] = A[M,K] @ W[N,K]^T (+ residual) ----------------
// 128x128 tile, BK=8, 256 threads, 8x8 microtile. All dims are multiples of
// 128 (M=4096; N in {256,1024,4096,32000}) and K multiple of 8 -> no guards.
template <int RES>
__global__ __launch_bounds__(256) void gemm_nt_kernel(
    const float* __restrict__ A, const float* __restrict__ W,
    const float* __restrict__ R, float* __restrict__ C, int N, int K) {
    __shared__ float As[8][128];
    __shared__ float Bs[8][128];
    int tid = threadIdx.x;
    int bm = blockIdx.y * 128, bn = blockIdx.x * 128;
    int lr = tid >> 1;            // 0..127 row in tile
    int lc = (tid & 1) * 4;       // 0 or 4
    const float* Ap = A + (size_t)(bm + lr) * K + lc;
    const float* Wp = W + (size_t)(bn + lr) * K + lc;
    int ty = tid >> 4, tx = tid & 15;
    float acc[8][8];
    #pragma unroll
    for (int i = 0; i < 8; i++)
        #pragma unroll
        for (int j = 0; j < 8; j++) acc[i][j] = 0.f;

    for (int k0 = 0; k0 < K; k0 += 8) {
        float4 a4 = *(const float4*)(Ap + k0);
        float4 b4 = *(const float4*)(Wp + k0);
        __syncthreads();
        As[lc + 0][lr] = a4.x; As[lc + 1][lr] = a4.y;
        As[lc + 2][lr] = a4.z; As[lc + 3][lr] = a4.w;
        Bs[lc + 0][lr] = b4.x; Bs[lc + 1][lr] = b4.y;
        Bs[lc + 2][lr] = b4.z; Bs[lc + 3][lr] = b4.w;
        __syncthreads();
        #pragma unroll
        for (int kk = 0; kk < 8; kk++) {
            float a[8], b[8];
            *(float4*)(a)     = *(const float4*)&As[kk][ty * 8];
            *(float4*)(a + 4) = *(const float4*)&As[kk][ty * 8 + 4];
            *(float4*)(b)     = *(const float4*)&Bs[kk][tx * 8];
            *(float4*)(b + 4) = *(const float4*)&Bs[kk][tx * 8 + 4];
            #pragma unroll
            for (int i = 0; i < 8; i++)
                #pragma unroll
                for (int j = 0; j < 8; j++) acc[i][j] += a[i] * b[j];
        }
    }
    #pragma unroll
    for (int i = 0; i < 8; i++) {
        size_t off = (size_t)(bm + ty * 8 + i) * N + bn + tx * 8;
        if (RES) {
            #pragma unroll
            for (int j = 0; j < 8; j++) acc[i][j] += R[off + j];
        }
        *(float4*)(C + off)     = make_float4(acc[i][0], acc[i][1], acc[i][2], acc[i][3]);
        *(float4*)(C + off + 4) = make_float4(acc[i][4], acc[i][5], acc[i][6], acc[i][7]);
    }
}

// ---------------- RoPE apply (interleaved-half rotation) ----------------
__global__ void rope_kernel(float* __restrict__ x, int nheads) {
    int idx = blockIdx.x * 256 + threadIdx.x;      // over TOK*nheads*32
    int i  = idx & 31;
    int hh = (idx >> 5) % nheads;
    int t  = idx / (32 * nheads);
    int s  = t & (SEQ - 1);                        // position in sequence
    float c  = g_cos[s * 32 + i];
    float sn = g_sin[s * 32 + i];
    float* p = x + (size_t)t * nheads * HDIM + hh * HDIM;
    float x1 = p[i], x2 = p[i + 32];
    p[i]      = x1 * c - x2 * sn;
    p[i + 32] = x2 * c + x1 * sn;
}

// ---------------- causal GQA flash attention ----------------
// grid (S/64, NH, B), 64 threads; thread owns one query row.
__global__ __launch_bounds__(64) void attn_kernel(
    const float* __restrict__ q, const float* __restrict__ k,
    const float* __restrict__ v, float* __restrict__ o) {
    __shared__ float Ks[64][64];
    __shared__ float Vs[64][64];
    __shared__ float Ss[64][64];   // [key][thread] — 48KB total, exactly at limit
    int qt = blockIdx.x, h = blockIdx.y, b = blockIdx.z;
    int g = h >> 2;                // kv head = h / NREP
    int tid = threadIdx.x;
    int qi = qt * 64 + tid;

    const float* qp = q + ((size_t)(b * SEQ + qi)) * (NHEAD * HDIM) + h * HDIM;
    float qr[64];
    #pragma unroll
    for (int d = 0; d < 64; d += 4) {
        float4 t4 = *(const float4*)(qp + d);
        qr[d] = t4.x * 0.125f; qr[d + 1] = t4.y * 0.125f;
        qr[d + 2] = t4.z * 0.125f; qr[d + 3] = t4.w * 0.125f;
    }
    float m = -1e30f, l = 0.f;
    float acc[64];
    #pragma unroll
    for (int d = 0; d < 64; d++) acc[d] = 0.f;

    for (int j = 0; j <= qt; j++) {
        const float* kp = k + ((size_t)(b * SEQ + j * 64)) * (KVHEAD * HDIM) + g * HDIM;
        const float* vp = v + ((size_t)(b * SEQ + j * 64)) * (KVHEAD * HDIM) + g * HDIM;
        __syncthreads();
        #pragma unroll
        for (int i = 0; i < 16; i++) {
            int idx = i * 64 + tid;
            int r = idx >> 4, c = (idx & 15) * 4;
            *(float4*)&Ks[r][c] = *(const float4*)(kp + (size_t)r * (KVHEAD * HDIM) + c);
            *(float4*)&Vs[r][c] = *(const float4*)(vp + (size_t)r * (KVHEAD * HDIM) + c);
        }
        __syncthreads();
        #pragma unroll
        for (int kk = 0; kk < 64; kk++) {
            float s = 0.f;
            #pragma unroll
            for (int d = 0; d < 64; d += 4) {
                float4 kv = *(const float4*)&Ks[kk][d];
                s += qr[d] * kv.x + qr[d + 1] * kv.y + qr[d + 2] * kv.z + qr[d + 3] * kv.w;
            }
            Ss[kk][tid] = s;
        }
        if (j == qt) {   // causal mask on diagonal tile: key index j*64+kk valid iff kk <= tid
            for (int kk = tid + 1; kk < 64; kk++) Ss[kk][tid] = -1e30f;
        }
        float tmax = -1e30f;
        #pragma unroll
        for (int kk = 0; kk < 64; kk++) tmax = fmaxf(tmax, Ss[kk][tid]);
        float nm = fmaxf(m, tmax);
        float corr = __expf(m - nm);
        l *= corr;
        #pragma unroll
        for (int d = 0; d < 64; d++) acc[d] *= corr;
        #pragma unroll
        for (int kk = 0; kk < 64; kk++) {
            float p = __expf(Ss[kk][tid] - nm);
            l += p;
            #pragma unroll
            for (int d = 0; d < 64; d += 4) {
                float4 vv = *(const float4*)&Vs[kk][d];
                acc[d]     += p * vv.x; acc[d + 1] += p * vv.y;
                acc[d + 2] += p * vv.z; acc[d + 3] += p * vv.w;
            }
        }
        m = nm;
    }
    float inv = 1.f / l;
    float* op = o + ((size_t)(b * SEQ + qi)) * (NHEAD * HDIM) + h * HDIM;
    #pragma unroll
    for (int d = 0; d < 64; d += 4)
        *(float4*)(op + d) = make_float4(acc[d] * inv, acc[d + 1] * inv,
                                         acc[d + 2] * inv, acc[d + 3] * inv);
}

// ---------------- SwiGLU: f1 = silu(f1) * f3 ----------------
__global__ void swiglu_kernel() {
    size_t i = (size_t)blockIdx.x * 256 + threadIdx.x;
    float a = g_f1[i];
    g_f1[i] = (a / (1.f + __expf(-a))) * g_f3[i];
}

// ---------------- host orchestration ----------------
extern "C" void kernel_launch(void* const* d_in, const int* in_sizes, int n_in,
                              void* d_out, int out_size) {
    const int*   ids = (const int*)d_in[0];
    const float* emb = (const float*)d_in[1];
    const float* wq  = (const float*)d_in[2];   // [L,1024,1024]
    const float* wk  = (const float*)d_in[3];   // [L, 256,1024]
    const float* wv  = (const float*)d_in[4];   // [L, 256,1024]
    const float* wo  = (const float*)d_in[5];   // [L,1024,1024]
    const float* n1  = (const float*)d_in[6];   // [L,1024]
    const float* n2  = (const float*)d_in[7];   // [L,1024]
    const float* w1  = (const float*)d_in[8];   // [L,4096,1024]
    const float* w2  = (const float*)d_in[9];   // [L,1024,4096]
    const float* w3  = (const float*)d_in[10];  // [L,4096,1024]
    const float* fnw = (const float*)d_in[11];  // [1024]
    float* out = (float*)d_out;

    float *h, *xn, *qb, *kb, *vb, *att, *f1, *f3;
    cudaGetSymbolAddress((void**)&h,   g_h);
    cudaGetSymbolAddress((void**)&xn,  g_xn);
    cudaGetSymbolAddress((void**)&qb,  g_q);
    cudaGetSymbolAddress((void**)&kb,  g_k);
    cudaGetSymbolAddress((void**)&vb,  g_v);
    cudaGetSymbolAddress((void**)&att, g_att);
    cudaGetSymbolAddress((void**)&f1,  g_f1);
    cudaGetSymbolAddress((void**)&f3,  g_f3);

    rope_init_kernel<<<SEQ, 32>>>();
    embed_kernel<<<TOK, 256>>>(ids, emb);

    for (int l = 0; l < NLAYER; l++) {
        rmsnorm_kernel<<<TOK, 256>>>(h, n1 + (size_t)l * DIM, xn);
        gemm_nt_kernel<0><<<dim3(DIM / 128, TOK / 128), 256>>>(
            xn, wq + (size_t)l * DIM * DIM, nullptr, qb, DIM, DIM);
        gemm_nt_kernel<0><<<dim3(256 / 128, TOK / 128), 256>>>(
            xn, wk + (size_t)l * 256 * DIM, nullptr, kb, 256, DIM);
        gemm_nt_kernel<0><<<dim3(256 / 128, TOK / 128), 256>>>(
            xn, wv + (size_t)l * 256 * DIM, nullptr, vb, 256, DIM);
        rope_kernel<<<(TOK * NHEAD * 32) / 256, 256>>>(qb, NHEAD);
        rope_kernel<<<(TOK * KVHEAD * 32) / 256, 256>>>(kb, KVHEAD);
        attn_kernel<<<dim3(SEQ / 64, NHEAD, BATCH), 64>>>(qb, kb, vb, att);
        gemm_nt_kernel<1><<<dim3(DIM / 128, TOK / 128), 256>>>(
            att, wo + (size_t)l * DIM * DIM, h, h, DIM, DIM);
        rmsnorm_kernel<<<TOK, 256>>>(h, n2 + (size_t)l * DIM, xn);
        gemm_nt_kernel<0><<<dim3(FF / 128, TOK / 128), 256>>>(
            xn, w1 + (size_t)l * FF * DIM, nullptr, f1, FF, DIM);
        gemm_nt_kernel<0><<<dim3(FF / 128, TOK / 128), 256>>>(
            xn, w3 + (size_t)l * FF * DIM, nullptr, f3, FF, DIM);
        swiglu_kernel<<<(TOK * FF) / 256, 256>>>();
        gemm_nt_kernel<1><<<dim3(DIM / 128, TOK / 128), 256>>>(
            f1, w2 + (size_t)l * DIM * FF, h, h, DIM, FF);
    }
    rmsnorm_kernel<<<TOK, 256>>>(h, fnw, xn);
    gemm_nt_kernel<0><<<dim3(VOCAB / 128, TOK / 128), 256>>>(
        xn, emb, nullptr, out, VOCAB, DIM);
}

// round 3
// speedup vs baseline: 1.8730x; 1.8730x over previous
#include <cuda_runtime.h>
#include <cuda_bf16.h>
#include <math.h>
#include <stdint.h>

#define SEQ    2048
#define BATCH  2
#define TOK    4096
#define DIM    1024
#define NHEAD  16
#define KVHEAD 4
#define HDIM   64
#define NLAYER 8
#define FF     4096
#define VOCAB  32000

typedef __nv_bfloat16 bf16;

// ---------------- scratch ----------------
__device__ float g_h   [TOK * DIM];
__device__ float g_qkv [TOK * 1536];          // [q(1024)|k(256)|v(256)]
__device__ float g_f13 [TOK * 8192];          // [f1(4096)|f3(4096)]
__device__ float g_cos [SEQ * 32];
__device__ float g_sin [SEQ * 32];
// expanded bf16 activations (A-operand: [hi|hi|lo])
__device__ bf16 g_xne [TOK * 3072];
__device__ bf16 g_atte[TOK * 3072];
__device__ bf16 g_f1e [TOK * 12288];
// expanded bf16 weights (B-operand: [hi|lo|hi])
__device__ bf16 e_wqkv[NLAYER * 1536 * 3072];
__device__ bf16 e_wo  [NLAYER * 1024 * 3072];
__device__ bf16 e_w13 [NLAYER * 8192 * 3072];
__device__ bf16 e_w2  [NLAYER * 1024 * 12288];
__device__ bf16 e_emb [VOCAB * 3072];

__device__ __forceinline__ void split2(float x, bf16& hi, bf16& lo) {
    hi = __float2bfloat16_rn(x);
    lo = __float2bfloat16_rn(x - __bfloat162float(hi));
}

// ---------------- weight expansion: out rows = [hi | lo | hi] ----------------
__global__ void expand_w_kernel(const float* __restrict__ in, bf16* __restrict__ out,
                                int K, int rows_pl, size_t lstride, int row_off) {
    size_t idx = (size_t)blockIdx.x * 256 + threadIdx.x;
    int rt = (int)(idx / K);
    int k  = (int)(idx % K);
    int l  = rt / rows_pl;
    int r  = rt % rows_pl;
    float x = in[idx];
    bf16 hi, lo; split2(x, hi, lo);
    bf16* o = out + (size_t)l * lstride + (size_t)(row_off + r) * (3 * K);
    o[k] = hi; o[K + k] = lo; o[2 * K + k] = hi;
}

// ---------------- RoPE tables ----------------
__global__ void rope_init_kernel() {
    int t = blockIdx.x, j = threadIdx.x;
    double inv   = pow(10000.0, -(2.0 * j) / 64.0);
    double r     = 81920.0 * inv / (2.0 * M_PI);
    double gamma = (r - 1.0) / 31.0;
    gamma = gamma < 0.0 ? 0.0 : (gamma > 1.0 ? 1.0 : gamma);
    double inv2  = inv * ((1.0 - gamma) / 40.0 + gamma);
    double c     = sqrt(0.1 * log(40.0) + 1.0);
    double ang   = (double)t * inv2 / c;
    g_cos[t * 32 + j] = (float)cos(ang);
    g_sin[t * 32 + j] = (float)sin(ang);
}

__global__ void embed_kernel(const int* __restrict__ ids, const float* __restrict__ emb) {
    int t = blockIdx.x;
    const float* src = emb + (size_t)ids[t] * DIM;
    float* dst = g_h + (size_t)t * DIM;
    for (int d = threadIdx.x; d < DIM; d += blockDim.x) dst[d] = src[d];
}

// ---------------- rmsnorm -> expanded bf16 [hi|hi|lo] ----------------
__global__ __launch_bounds__(256) void rmsnorm_expand_kernel(
    const float* __restrict__ x, const float* __restrict__ w, bf16* __restrict__ o) {
    int row = blockIdx.x, tid = threadIdx.x;
    const float* xr = x + (size_t)row * DIM;
    float s = 0.f;
    for (int d = tid; d < DIM; d += 256) { float v = xr[d]; s += v * v; }
    #pragma unroll
    for (int off = 16; off; off >>= 1) s += __shfl_xor_sync(0xffffffffu, s, off);
    __shared__ float red[8]; __shared__ float rsv;
    if ((tid & 31) == 0) red[tid >> 5] = s;
    __syncthreads();
    if (tid == 0) {
        float t = 0.f;
        #pragma unroll
        for (int i = 0; i < 8; i++) t += red[i];
        rsv = rsqrtf(t / (float)DIM + 1e-6f);
    }
    __syncthreads();
    float rs = rsv;
    bf16* orow = o + (size_t)row * 3072;
    for (int d = tid; d < DIM; d += 256) {
        float y = xr[d] * rs * w[d];
        bf16 hi, lo; split2(y, hi, lo);
        orow[d] = hi; orow[1024 + d] = hi; orow[2048 + d] = lo;
    }
}

// ================= bf16 tensor-core GEMM (split-K expanded) =================
// C[M,N](f32) = Ae[M,K'](bf16) @ We[N,K'](bf16)^T (+R)
// CTA 128x256, BK=32 bf16 (64B rows), 256 thr, warp 64x64 = 4x8 m16n8k16.
#define BM 128
#define BN 256
#define BKE 32
#define A_BYTES (BM * BKE * 2)             // 8192
#define B_BYTES (BN * BKE * 2)             // 16384
#define STAGE_BYTES (A_BYTES + B_BYTES)    // 24576

__device__ __forceinline__ uint32_t swz(uint32_t r, uint32_t kf) {
    return (r * 4u + (kf ^ ((r >> 1) & 3u))) << 4;
}
#define CP_ASYNC16(dst, src) \
    asm volatile("cp.async.cg.shared.global [%0], [%1], 16;" :: "r"(dst), "l"(src))
#define CP_COMMIT()  asm volatile("cp.async.commit_group;")
#define CP_WAIT1()   asm volatile("cp.async.wait_group 1;")
#define LDSM_X4(r0, r1, r2, r3, addr) \
    asm volatile("ldmatrix.sync.aligned.m8n8.x4.shared.b16 {%0,%1,%2,%3}, [%4];" \
        : "=r"(r0), "=r"(r1), "=r"(r2), "=r"(r3) : "r"(addr))
#define MMA_BF16(c, a0, a1, a2, a3, b0, b1) \
    asm volatile("mma.sync.aligned.m16n8k16.row.col.f32.bf16.bf16.f32 " \
        "{%0,%1,%2,%3}, {%4,%5,%6,%7}, {%8,%9}, {%0,%1,%2,%3};" \
        : "+f"(c[0]), "+f"(c[1]), "+f"(c[2]), "+f"(c[3]) \
        : "r"(a0), "r"(a1), "r"(a2), "r"(a3), "r"(b0), "r"(b1))

template <int RES>
__global__ __launch_bounds__(256, 1) void gemm_bf(
    const bf16* __restrict__ A, const bf16* __restrict__ W,
    const float* __restrict__ R, float* __restrict__ C, int N, int K) {
    __shared__ __align__(16) char smem[2 * STAGE_BYTES];   // 48KB
    const int tid  = threadIdx.x;
    const int lane = tid & 31;
    const int wid  = tid >> 5;
    const int wm   = wid >> 2;
    const int wn   = wid & 3;
    const int bm   = blockIdx.y * BM;
    const int bn   = blockIdx.x * BN;
    const uint32_t smem_u = (uint32_t)__cvta_generic_to_shared(smem);

    const int lr = tid >> 2;
    const int kf = tid & 3;
    const bf16* Ag0 = A + (size_t)(bm + lr)      * K + kf * 8;
    const bf16* Ag1 = A + (size_t)(bm + lr + 64) * K + kf * 8;
    const bf16* Wg0 = W + (size_t)(bn + lr)       * K + kf * 8;
    const bf16* Wg1 = W + (size_t)(bn + lr + 64)  * K + kf * 8;
    const bf16* Wg2 = W + (size_t)(bn + lr + 128) * K + kf * 8;
    const bf16* Wg3 = W + (size_t)(bn + lr + 192) * K + kf * 8;
    const uint32_t aO0 = swz(lr, kf),       aO1 = swz(lr + 64, kf);
    const uint32_t bO0 = swz(lr, kf),       bO1 = swz(lr + 64, kf);
    const uint32_t bO2 = swz(lr + 128, kf), bO3 = swz(lr + 192, kf);

    const int flr = lane & 15;
    const int fhi = lane >> 4;
    uint32_t a_off[2][4];
    #pragma unroll
    for (int s = 0; s < 2; s++)
        #pragma unroll
        for (int i = 0; i < 4; i++)
            a_off[s][i] = swz(wm * 64 + i * 16 + flr, 2 * s + fhi);
    const int brow_b = wn * 64 + (lane & 7) + fhi * 8;
    const int bkf_h  = (lane >> 3) & 1;
    uint32_t b_off[2][4];
    #pragma unroll
    for (int s = 0; s < 2; s++)
        #pragma unroll
        for (int p = 0; p < 4; p++)
            b_off[s][p] = (uint32_t)A_BYTES + swz(brow_b + p * 16, 2 * s + bkf_h);

    float acc[4][8][4];
    #pragma unroll
    for (int i = 0; i < 4; i++)
        #pragma unroll
        for (int j = 0; j < 8; j++)
            #pragma unroll
            for (int q = 0; q < 4; q++) acc[i][j][q] = 0.f;

    const int nk = K / BKE;
    {
        uint32_t base = smem_u;
        CP_ASYNC16(base + aO0, Ag0); CP_ASYNC16(base + aO1, Ag1);
        uint32_t bb = base + A_BYTES;
        CP_ASYNC16(bb + bO0, Wg0); CP_ASYNC16(bb + bO1, Wg1);
        CP_ASYNC16(bb + bO2, Wg2); CP_ASYNC16(bb + bO3, Wg3);
        CP_COMMIT();
    }

    for (int kt = 0; kt < nk; kt++) {
        if (kt + 1 < nk) {
            int k0 = (kt + 1) * BKE;
            uint32_t base = smem_u + ((kt + 1) & 1) * STAGE_BYTES;
            CP_ASYNC16(base + aO0, Ag0 + k0); CP_ASYNC16(base + aO1, Ag1 + k0);
            uint32_t bb = base + A_BYTES;
            CP_ASYNC16(bb + bO0, Wg0 + k0); CP_ASYNC16(bb + bO1, Wg1 + k0);
            CP_ASYNC16(bb + bO2, Wg2 + k0); CP_ASYNC16(bb + bO3, Wg3 + k0);
        }
        CP_COMMIT();
        CP_WAIT1();
        __syncthreads();

        uint32_t cbase = smem_u + (kt & 1) * STAGE_BYTES;
        #pragma unroll
        for (int s = 0; s < 2; s++) {
            uint32_t af[4][4];
            #pragma unroll
            for (int i = 0; i < 4; i++)
                LDSM_X4(af[i][0], af[i][1], af[i][2], af[i][3], cbase + a_off[s][i]);
            #pragma unroll
            for (int p = 0; p < 4; p++) {
                uint32_t b0, b1, b2, b3;
                LDSM_X4(b0, b1, b2, b3, cbase + b_off[s][p]);
                #pragma unroll
                for (int i = 0; i < 4; i++) {
                    MMA_BF16(acc[i][2 * p],     af[i][0], af[i][1], af[i][2], af[i][3], b0, b1);
                    MMA_BF16(acc[i][2 * p + 1], af[i][0], af[i][1], af[i][2], af[i][3], b2, b3);
                }
            }
        }
        __syncthreads();
    }

    const int gid = lane >> 2, tig = lane & 3;
    #pragma unroll
    for (int i = 0; i < 4; i++) {
        int r0 = bm + wm * 64 + i * 16 + gid;
        #pragma unroll
        for (int j = 0; j < 8; j++) {
            int c0 = bn + wn * 64 + j * 8 + tig * 2;
            size_t o0 = (size_t)r0 * N + c0;
            size_t o1 = o0 + (size_t)8 * N;
            float2 v0 = make_float2(acc[i][j][0], acc[i][j][1]);
            float2 v1 = make_float2(acc[i][j][2], acc[i][j][3]);
            if (RES) {
                float2 ra = *(const float2*)(R + o0);
                float2 rb = *(const float2*)(R + o1);
                v0.x += ra.x; v0.y += ra.y; v1.x += rb.x; v1.y += rb.y;
            }
            *(float2*)(C + o0) = v0;
            *(float2*)(C + o1) = v1;
        }
    }
}

// ---------------- RoPE on qkv slab ----------------
__global__ void rope_kernel(float* __restrict__ x, int nheads, int off) {
    int idx = blockIdx.x * 256 + threadIdx.x;
    int i  = idx & 31;
    int hh = (idx >> 5) % nheads;
    int t  = idx / (32 * nheads);
    int s  = t & (SEQ - 1);
    float c  = g_cos[s * 32 + i];
    float sn = g_sin[s * 32 + i];
    float* p = x + (size_t)t * 1536 + off + hh * HDIM;
    float x1 = p[i], x2 = p[i + 32];
    p[i]      = x1 * c - x2 * sn;
    p[i + 32] = x2 * c + x1 * sn;
}

// ---------------- causal GQA flash attention (qkv slab in, expanded out) ----------------
__global__ __launch_bounds__(64) void attn_kernel(
    const float* __restrict__ qkv, bf16* __restrict__ oe) {
    __shared__ float Ks[64][64];
    __shared__ float Vs[64][64];
    __shared__ float Ss[64][64];
    int qt = blockIdx.x, h = blockIdx.y, b = blockIdx.z;
    int g = h >> 2;
    int tid = threadIdx.x;
    int qi = qt * 64 + tid;

    const float* qp = qkv + (size_t)(b * SEQ + qi) * 1536 + h * HDIM;
    float qr[64];
    #pragma unroll
    for (int d = 0; d < 64; d += 4) {
        float4 t4 = *(const float4*)(qp + d);
        qr[d] = t4.x * 0.125f; qr[d + 1] = t4.y * 0.125f;
        qr[d + 2] = t4.z * 0.125f; qr[d + 3] = t4.w * 0.125f;
    }
    float m = -1e30f, l = 0.f;
    float acc[64];
    #pragma unroll
    for (int d = 0; d < 64; d++) acc[d] = 0.f;

    for (int j = 0; j <= qt; j++) {
        const float* kp = qkv + (size_t)(b * SEQ + j * 64) * 1536 + 1024 + g * HDIM;
        const float* vp = kp + 256;
        __syncthreads();
        #pragma unroll
        for (int i = 0; i < 16; i++) {
            int idx = i * 64 + tid;
            int r = idx >> 4, c = (idx & 15) * 4;
            *(float4*)&Ks[r][c] = *(const float4*)(kp + (size_t)r * 1536 + c);
            *(float4*)&Vs[r][c] = *(const float4*)(vp + (size_t)r * 1536 + c);
        }
        __syncthreads();
        #pragma unroll
        for (int kk = 0; kk < 64; kk++) {
            float s = 0.f;
            #pragma unroll
            for (int d = 0; d < 64; d += 4) {
                float4 kv = *(const float4*)&Ks[kk][d];
                s += qr[d] * kv.x + qr[d + 1] * kv.y + qr[d + 2] * kv.z + qr[d + 3] * kv.w;
            }
            Ss[kk][tid] = s;
        }
        if (j == qt) {
            for (int kk = tid + 1; kk < 64; kk++) Ss[kk][tid] = -1e30f;
        }
        float tmax = -1e30f;
        #pragma unroll
        for (int kk = 0; kk < 64; kk++) tmax = fmaxf(tmax, Ss[kk][tid]);
        float nm = fmaxf(m, tmax);
        float corr = __expf(m - nm);
        l *= corr;
        #pragma unroll
        for (int d = 0; d < 64; d++) acc[d] *= corr;
        #pragma unroll
        for (int kk = 0; kk < 64; kk++) {
            float p = __expf(Ss[kk][tid] - nm);
            l += p;
            #pragma unroll
            for (int d = 0; d < 64; d += 4) {
                float4 vv = *(const float4*)&Vs[kk][d];
                acc[d]     += p * vv.x; acc[d + 1] += p * vv.y;
                acc[d + 2] += p * vv.z; acc[d + 3] += p * vv.w;
            }
        }
        m = nm;
    }
    float inv = 1.f / l;
    bf16* op = oe + (size_t)(b * SEQ + qi) * 3072 + h * HDIM;
    #pragma unroll
    for (int d = 0; d < 64; d += 2) {
        float y0 = acc[d] * inv, y1 = acc[d + 1] * inv;
        bf16 h0, l0, h1, l1;
        split2(y0, h0, l0); split2(y1, h1, l1);
        *(__nv_bfloat162*)(op + d)        = __nv_bfloat162(h0, h1);
        *(__nv_bfloat162*)(op + 1024 + d) = __nv_bfloat162(h0, h1);
        *(__nv_bfloat162*)(op + 2048 + d) = __nv_bfloat162(l0, l1);
    }
}

// ---------------- SwiGLU -> expanded [hi|hi|lo] ----------------
__global__ void swiglu_expand_kernel() {
    int i = blockIdx.x * 256 + threadIdx.x;   // over TOK*FF
    int t = i >> 12, c = i & 4095;
    float a = g_f13[(size_t)t * 8192 + c];
    float b = g_f13[(size_t)t * 8192 + 4096 + c];
    float u = (a / (1.f + __expf(-a))) * b;
    bf16 hi, lo; split2(u, hi, lo);
    bf16* o = g_f1e + (size_t)t * 12288;
    o[c] = hi; o[4096 + c] = hi; o[8192 + c] = lo;
}

// ---------------- host orchestration ----------------
extern "C" void kernel_launch(void* const* d_in, const int* in_sizes, int n_in,
                              void* d_out, int out_size) {
    const int*   ids = (const int*)d_in[0];
    const float* emb = (const float*)d_in[1];
    const float* wq  = (const float*)d_in[2];
    const float* wk  = (const float*)d_in[3];
    const float* wv  = (const float*)d_in[4];
    const float* wo  = (const float*)d_in[5];
    const float* n1  = (const float*)d_in[6];
    const float* n2  = (const float*)d_in[7];
    const float* w1  = (const float*)d_in[8];
    const float* w2  = (const float*)d_in[9];
    const float* w3  = (const float*)d_in[10];
    const float* fnw = (const float*)d_in[11];
    float* out = (float*)d_out;

    float *h, *qkv, *f13;
    bf16 *xne, *atte, *f1e, *ewqkv, *ewo, *ew13, *ew2, *eemb;
    cudaGetSymbolAddress((void**)&h,     g_h);
    cudaGetSymbolAddress((void**)&qkv,   g_qkv);
    cudaGetSymbolAddress((void**)&f13,   g_f13);
    cudaGetSymbolAddress((void**)&xne,   g_xne);
    cudaGetSymbolAddress((void**)&atte,  g_atte);
    cudaGetSymbolAddress((void**)&f1e,   g_f1e);
    cudaGetSymbolAddress((void**)&ewqkv, e_wqkv);
    cudaGetSymbolAddress((void**)&ewo,   e_wo);
    cudaGetSymbolAddress((void**)&ew13,  e_w13);
    cudaGetSymbolAddress((void**)&ew2,   e_w2);
    cudaGetSymbolAddress((void**)&eemb,  e_emb);

    // ---- expand all weights (bf16 hi/lo triple) ----
    expand_w_kernel<<<(NLAYER * 1024 * 1024) / 256, 256>>>(wq, ewqkv, 1024, 1024, (size_t)1536 * 3072, 0);
    expand_w_kernel<<<(NLAYER * 256  * 1024) / 256, 256>>>(wk, ewqkv, 1024, 256,  (size_t)1536 * 3072, 1024);
    expand_w_kernel<<<(NLAYER * 256  * 1024) / 256, 256>>>(wv, ewqkv, 1024, 256,  (size_t)1536 * 3072, 1280);
    expand_w_kernel<<<(NLAYER * 1024 * 1024) / 256, 256>>>(wo, ewo,   1024, 1024, (size_t)1024 * 3072, 0);
    expand_w_kernel<<<(NLAYER * 4096 * 1024) / 256, 256>>>(w1, ew13,  1024, 4096, (size_t)8192 * 3072, 0);
    expand_w_kernel<<<(NLAYER * 4096 * 1024) / 256, 256>>>(w3, ew13,  1024, 4096, (size_t)8192 * 3072, 4096);
    expand_w_kernel<<<(NLAYER * 1024 * 4096) / 256, 256>>>(w2, ew2,   4096, 1024, (size_t)1024 * 12288, 0);
    expand_w_kernel<<<(VOCAB * 1024) / 256, 256>>>(emb, eemb, 1024, VOCAB, 0, 0);

    rope_init_kernel<<<SEQ, 32>>>();
    embed_kernel<<<TOK, 256>>>(ids, emb);

    for (int l = 0; l < NLAYER; l++) {
        rmsnorm_expand_kernel<<<TOK, 256>>>(h, n1 + (size_t)l * DIM, xne);
        gemm_bf<0><<<dim3(1536 / BN, TOK / BM), 256>>>(
            xne, ewqkv + (size_t)l * 1536 * 3072, nullptr, qkv, 1536, 3072);
        rope_kernel<<<(TOK * NHEAD * 32) / 256, 256>>>(qkv, NHEAD, 0);
        rope_kernel<<<(TOK * KVHEAD * 32) / 256, 256>>>(qkv, KVHEAD, 1024);
        attn_kernel<<<dim3(SEQ / 64, NHEAD, BATCH), 64>>>(qkv, atte);
        gemm_bf<1><<<dim3(1024 / BN, TOK / BM), 256>>>(
            atte, ewo + (size_t)l * 1024 * 3072, h, h, 1024, 3072);
        rmsnorm_expand_kernel<<<TOK, 256>>>(h, n2 + (size_t)l * DIM, xne);
        gemm_bf<0><<<dim3(8192 / BN, TOK / BM), 256>>>(
            xne, ew13 + (size_t)l * 8192 * 3072, nullptr, f13, 8192, 3072);
        swiglu_expand_kernel<<<(TOK * FF) / 256, 256>>>();
        gemm_bf<1><<<dim3(1024 / BN, TOK / BM), 256>>>(
            f1e, ew2 + (size_t)l * 1024 * 12288, h, h, 1024, 12288);
    }
    rmsnorm_expand_kernel<<<TOK, 256>>>(h, fnw, xne);
    gemm_bf<0><<<dim3(VOCAB / BN, TOK / BM), 256>>>(
        xne, eemb, nullptr, out, VOCAB, 3072);
}